// round 6
// baseline (speedup 1.0000x reference)
#include <cuda_runtime.h>
#include <cstdint>

// YOLO post-process: (16, 25200, 85) fp32 -> (16, 25200, 6) fp32
//
// R5: persistent blocks + depth-4 cp.async.bulk pipeline + atomic ticket scheduler.
//   - 64-row tiles (21760 B), 4 input buffers per block -> copy queue never drains
//   - global ticket counter for near-perfect balance (reset kernel each launch)
//   - 64 threads/block, thread-per-row compute out of smem (stride-85 LDS = conflict-free)
//   - 4-way unrolled argmax, ordered merge (first-index tie-break)

#define N_ROWS        403200          // 16 * 25200
#define N_CH          85
#define N_OUT         6
#define CONF_TH       0.25f
#define TILE_ROWS     64
#define NT            (N_ROWS / TILE_ROWS)   // 6300
#define DEPTH         4
#define BLOCK_THREADS 64
#define TILE_FLOATS   (TILE_ROWS * N_CH)     // 5440
#define TILE_BYTES    (TILE_FLOATS * 4)      // 21760
#define OUT_FLOATS    (TILE_ROWS * N_OUT)    // 384
#define OUT_VEC4      (OUT_FLOATS / 4)       // 96
#define GRID_BLOCKS   296                    // 2 per SM * 148

// dynamic smem layout:
//   [0,32)    mbar[4]
//   [32,48)   ticket queue tq[4]
//   [64, +4*TILE_BYTES)  in bufs
//   then 2 out bufs of 1536 B
#define SM_IN    64
#define SM_OUT   (SM_IN + DEPTH * TILE_BYTES)          // 64 + 87040 = 87104
#define SM_TOTAL (SM_OUT + 2 * OUT_FLOATS * 4)         // 90176

__device__ unsigned g_ticket;

__global__ void reset_ticket_kernel() { g_ticket = 0u; }

__device__ __forceinline__ unsigned smem_u32(const void* p) {
    unsigned a;
    asm("{ .reg .u64 t; cvta.to.shared.u64 t, %1; cvt.u32.u64 %0, t; }"
        : "=r"(a) : "l"(p));
    return a;
}

__device__ __forceinline__ void mbar_init(unsigned addr, unsigned count) {
    asm volatile("mbarrier.init.shared.b64 [%0], %1;" :: "r"(addr), "r"(count) : "memory");
}

__device__ __forceinline__ void bulk_load(unsigned dst_smem, const void* gsrc,
                                          unsigned bytes, unsigned mbar) {
    asm volatile("mbarrier.arrive.expect_tx.shared.b64 _, [%0], %1;"
                 :: "r"(mbar), "r"(bytes) : "memory");
    asm volatile("cp.async.bulk.shared::cta.global.mbarrier::complete_tx::bytes "
                 "[%0], [%1], %2, [%3];"
                 :: "r"(dst_smem), "l"(gsrc), "r"(bytes), "r"(mbar) : "memory");
}

__device__ __forceinline__ void mbar_wait(unsigned addr, unsigned parity) {
    asm volatile(
        "{\n\t"
        ".reg .pred P;\n\t"
        "W%=:\n\t"
        "mbarrier.try_wait.parity.acquire.cta.shared::cta.b64 P, [%0], %1, 0x989680;\n\t"
        "@P bra D%=;\n\t"
        "bra W%=;\n\t"
        "D%=:\n\t"
        "}"
        :: "r"(addr), "r"(parity) : "memory");
}

__global__ __launch_bounds__(BLOCK_THREADS, 2)
void yolo_post_kernel(const float* __restrict__ in, float4* __restrict__ out4)
{
    extern __shared__ char sb[];
    const unsigned base = smem_u32(sb);
    int* const tq = reinterpret_cast<int*>(sb + 32);
    float* const in_base = reinterpret_cast<float*>(sb + SM_IN);
    float* const out_base = reinterpret_cast<float*>(sb + SM_OUT);

    const int tid = threadIdx.x;

    if (tid == 0) {
        #pragma unroll
        for (int b = 0; b < DEPTH; b++) mbar_init(base + b * 8, 1);
    }
    __syncthreads();

    // Prologue: fetch first DEPTH-1 tickets and launch their DMAs.
    if (tid == 0) {
        #pragma unroll
        for (int s = 0; s < DEPTH - 1; s++) {
            int t = (int)atomicAdd(&g_ticket, 1u);
            tq[s] = t;
            if (t < NT) {
                bulk_load(base + SM_IN + s * TILE_BYTES,
                          in + (size_t)t * TILE_FLOATS, TILE_BYTES, base + s * 8);
            }
        }
    }
    __syncthreads();

    for (int it = 0; ; ++it) {
        // Fetch ticket & issue DMA for the slot that frees up this iteration.
        // Buffer (it-1)&3 was fully consumed before the syncthreads of iter it-1.
        const int slot_w = (it + DEPTH - 1) & (DEPTH - 1);
        if (tid == 0) {
            int t = (int)atomicAdd(&g_ticket, 1u);
            tq[slot_w] = t;
            if (t < NT) {
                bulk_load(base + SM_IN + slot_w * TILE_BYTES,
                          in + (size_t)t * TILE_FLOATS, TILE_BYTES, base + slot_w * 8);
            }
        }

        // Consume oldest pending slot.
        const int slot = it & (DEPTH - 1);
        const int tile = tq[slot];             // written >= DEPTH-1 iters / 1 sync ago
        if (tile >= NT) break;                  // monotone tickets: nothing valid remains

        mbar_wait(base + slot * 8, (unsigned)((it >> 2) & 1));

        // ---- compute: thread-per-row ----
        const float* row = in_base + slot * TILE_FLOATS + tid * N_CH;

        const float x    = row[0];
        const float y    = row[1];
        const float w    = row[2];
        const float h    = row[3];
        const float conf = row[4];

        float b0 = row[5 +  0], b1 = row[5 + 20], b2 = row[5 + 40], b3 = row[5 + 60];
        int   i0 = 0,           i1 = 20,          i2 = 40,          i3 = 60;

        #pragma unroll
        for (int c = 1; c < 20; c++) {
            float v0 = row[5 +  0 + c];
            float v1 = row[5 + 20 + c];
            float v2 = row[5 + 40 + c];
            float v3 = row[5 + 60 + c];
            if (v0 > b0) { b0 = v0; i0 =  0 + c; }
            if (v1 > b1) { b1 = v1; i1 = 20 + c; }
            if (v2 > b2) { b2 = v2; i2 = 40 + c; }
            if (v3 > b3) { b3 = v3; i3 = 60 + c; }
        }
        // Ordered merge: ties keep the earlier quarter -> first-index semantics.
        if (b1 > b0) { b0 = b1; i0 = i1; }
        if (b2 > b0) { b0 = b2; i0 = i2; }
        if (b3 > b0) { b0 = b3; i0 = i3; }

        const float score = conf * b0;
        const bool  pass  = score > CONF_TH;
        const float hw = 0.5f * w;
        const float hh = 0.5f * h;

        float o0 = 0.f, o1 = 0.f, o2 = 0.f, o3 = 0.f, o4 = 0.f, o5 = 0.f;
        if (pass) {
            o0 = x - hw;
            o1 = y - hh;
            o2 = x + hw;
            o3 = y + hh;
            o4 = score;
            o5 = (float)i0;
        }

        // ---- stage outputs (alternate buffers), coalesced store ----
        float* ob = out_base + (it & 1) * OUT_FLOATS;
        float* so = ob + tid * N_OUT;
        so[0] = o0; so[1] = o1; so[2] = o2; so[3] = o3; so[4] = o4; so[5] = o5;
        __syncthreads();   // orders: all LDS reads done (DMA reuse safe), staging visible

        {
            const float4* src = reinterpret_cast<const float4*>(ob);
            float4* dst = out4 + (size_t)tile * OUT_VEC4;
            #pragma unroll
            for (int i = tid; i < OUT_VEC4; i += BLOCK_THREADS)
                dst[i] = src[i];
        }
    }
}

extern "C" void kernel_launch(void* const* d_in, const int* in_sizes, int n_in,
                              void* d_out, int out_size)
{
    const float* in  = (const float*)d_in[0];
    float4*      out = (float4*)d_out;
    reset_ticket_kernel<<<1, 1>>>();
    cudaFuncSetAttribute(yolo_post_kernel,
                         cudaFuncAttributeMaxDynamicSharedMemorySize, SM_TOTAL);
    yolo_post_kernel<<<GRID_BLOCKS, BLOCK_THREADS, SM_TOTAL>>>(in, out);
}